// round 14
// baseline (speedup 1.0000x reference)
#include <cuda_runtime.h>
#include <cuda_bf16.h>
#include <cstdint>

#define B_   128
#define T_   1024
#define IN_  128
#define H_   256
#define G3   768          // 3*H
#define NOUT 4

// ---------------------------------------------------------------------------
// Static device scratch (no cudaMalloc allowed).
// ---------------------------------------------------------------------------
__device__ float    g_px0[2 * T_ * B_ * G3];
__device__ float    g_px1[2 * T_ * B_ * G3];
__device__ float    g_y0 [T_ * B_ * 2 * H_];
__device__ unsigned g_h  [2 * 2 * 2 * B_ * H_];    // packed (bf16hi|bf16lo) h
__device__ float    g_hlast[2 * B_ * H_];
__device__ unsigned g_flags[2 * 2 * 8 * 8];        // [layer][dir][bg][slice slot]

__global__ void zero_kernel() {
    const int n1 = 2 * 2 * 2 * B_ * H_;
    const int n2 = 2 * 2 * 8 * 8;
    int stride = gridDim.x * blockDim.x;
    for (int i = blockIdx.x * blockDim.x + threadIdx.x; i < n1; i += stride)
        g_h[i] = 0u;
    for (int i = blockIdx.x * blockDim.x + threadIdx.x; i < n2; i += stride)
        g_flags[i] = 0u;
}

// ---------------------------------------------------------------------------
// Tensor-core projection GEMM (3xTF32 split). Unchanged.
// ---------------------------------------------------------------------------
#define TC_SMEM (4 * 128 * 36 * 4)

__device__ __forceinline__ unsigned f2tf(float x) {
    unsigned r; asm("cvt.rna.tf32.f32 %0, %1;" : "=r"(r) : "f"(x)); return r;
}

__device__ __forceinline__ void mma_tf32(float* c, const unsigned* a, const unsigned* b) {
    asm volatile("mma.sync.aligned.m16n8k8.row.col.f32.tf32.tf32.f32 "
                 "{%0,%1,%2,%3}, {%4,%5,%6,%7}, {%8,%9}, {%0,%1,%2,%3};"
                 : "+f"(c[0]), "+f"(c[1]), "+f"(c[2]), "+f"(c[3])
                 : "r"(a[0]), "r"(a[1]), "r"(a[2]), "r"(a[3]),
                   "r"(b[0]), "r"(b[1]));
}

__device__ __forceinline__ void px_scatter(float v, int m, int n, int mode,
                                           const float* __restrict__ bias,
                                           float* __restrict__ out) {
    int t, b;
    if (mode == 0) { b = m >> 10; t = m & (T_ - 1); }
    else           { t = m >> 7;  b = m & (B_ - 1); }
    int dir = (n >= G3) ? 1 : 0;
    int g   = n - dir * G3;
    out[((size_t)(dir * T_ + t) * B_ + b) * G3 + g] = v + __ldg(&bias[n]);
}

__global__ __launch_bounds__(256, 1)
void gemm_proj_tc(const float* __restrict__ A, const float* __restrict__ W,
                  const float* __restrict__ bias, float* __restrict__ out,
                  int K, int mode)
{
    extern __shared__ unsigned sm_u[];
    unsigned* Ah = sm_u;
    unsigned* Al = Ah + 128 * 36;
    unsigned* Bh = Al + 128 * 36;
    unsigned* Bl = Bh + 128 * 36;

    const int tid  = threadIdx.x;
    const int n0   = blockIdx.x * 128;
    const int m0   = blockIdx.y * 128;
    const int wid  = tid >> 5;
    const int lane = tid & 31;
    const int wm   = (wid & 3) * 32;
    const int wn   = (wid >> 2) * 64;
    const int g    = lane >> 2;
    const int tg   = lane & 3;

    float acc[2][8][4];
#pragma unroll
    for (int mt = 0; mt < 2; mt++)
#pragma unroll
        for (int nt = 0; nt < 8; nt++)
#pragma unroll
            for (int j = 0; j < 4; j++) acc[mt][nt][j] = 0.0f;

    for (int k0 = 0; k0 < K; k0 += 32) {
#pragma unroll
        for (int i = 0; i < 4; i++) {
            int e = tid + i * 256;
            int r = e >> 3;
            int c = (e & 7) * 4;

            float4 va = *(const float4*)&A[(size_t)(m0 + r) * K + k0 + c];
            unsigned h0 = f2tf(va.x), h1 = f2tf(va.y),
                     h2 = f2tf(va.z), h3 = f2tf(va.w);
            *(uint4*)&Ah[r * 36 + c] = make_uint4(h0, h1, h2, h3);
            *(uint4*)&Al[r * 36 + c] = make_uint4(
                f2tf(va.x - __uint_as_float(h0)),
                f2tf(va.y - __uint_as_float(h1)),
                f2tf(va.z - __uint_as_float(h2)),
                f2tf(va.w - __uint_as_float(h3)));

            float4 vb = *(const float4*)&W[(size_t)(n0 + r) * K + k0 + c];
            unsigned p0 = f2tf(vb.x), p1 = f2tf(vb.y),
                     p2 = f2tf(vb.z), p3 = f2tf(vb.w);
            *(uint4*)&Bh[r * 36 + c] = make_uint4(p0, p1, p2, p3);
            *(uint4*)&Bl[r * 36 + c] = make_uint4(
                f2tf(vb.x - __uint_as_float(p0)),
                f2tf(vb.y - __uint_as_float(p1)),
                f2tf(vb.z - __uint_as_float(p2)),
                f2tf(vb.w - __uint_as_float(p3)));
        }
        __syncthreads();

#pragma unroll
        for (int kk = 0; kk < 4; kk++) {
            const int kc = kk * 8 + tg;
            unsigned ah[2][4], al[2][4], bh[8][2], bl[8][2];
#pragma unroll
            for (int mt = 0; mt < 2; mt++) {
                int m = wm + mt * 16;
                ah[mt][0] = Ah[(m + g) * 36 + kc];
                ah[mt][1] = Ah[(m + 8 + g) * 36 + kc];
                ah[mt][2] = Ah[(m + g) * 36 + kc + 4];
                ah[mt][3] = Ah[(m + 8 + g) * 36 + kc + 4];
                al[mt][0] = Al[(m + g) * 36 + kc];
                al[mt][1] = Al[(m + 8 + g) * 36 + kc];
                al[mt][2] = Al[(m + g) * 36 + kc + 4];
                al[mt][3] = Al[(m + 8 + g) * 36 + kc + 4];
            }
#pragma unroll
            for (int nt = 0; nt < 8; nt++) {
                int n = wn + nt * 8;
                bh[nt][0] = Bh[(n + g) * 36 + kc];
                bh[nt][1] = Bh[(n + g) * 36 + kc + 4];
                bl[nt][0] = Bl[(n + g) * 36 + kc];
                bl[nt][1] = Bl[(n + g) * 36 + kc + 4];
            }
#pragma unroll
            for (int mt = 0; mt < 2; mt++)
#pragma unroll
                for (int nt = 0; nt < 8; nt++) {
                    mma_tf32(acc[mt][nt], ah[mt], bh[nt]);
                    mma_tf32(acc[mt][nt], ah[mt], bl[nt]);
                    mma_tf32(acc[mt][nt], al[mt], bh[nt]);
                }
        }
        __syncthreads();
    }

#pragma unroll
    for (int mt = 0; mt < 2; mt++) {
#pragma unroll
        for (int nt = 0; nt < 8; nt++) {
            int m = m0 + wm + mt * 16 + g;
            int n = n0 + wn + nt * 8 + tg * 2;
            px_scatter(acc[mt][nt][0], m,     n,     mode, bias, out);
            px_scatter(acc[mt][nt][1], m,     n + 1, mode, bias, out);
            px_scatter(acc[mt][nt][2], m + 8, n,     mode, bias, out);
            px_scatter(acc[mt][nt][3], m + 8, n + 1, mode, bias, out);
        }
    }
}

// ---------------------------------------------------------------------------
// Tensor-core GRU scan (bf16 hi/lo K-concat), warp-specialized pipeline:
//  - warps 0-3: MMA (K' low half), gates, h publish, flag release
//  - warps 4-7: MMA (K' high half), partials, then POLL + STAGE step s+1
//    into the other hA parity buffer while gate warps run the tail.
//  - flags: 8 per-CTA slots in one 32B sector; st.release / coalesced
//    acquire-poll of the whole sector by warp 4.
//  - B' fragments register-resident (R12). hA parity double buffer (R11).
// Grid (8 bg, 8 slice, 2 dir) = 128 CTAs, 256 threads, 1 CTA/SM.
// ---------------------------------------------------------------------------
#define WP_WORDS (96 * 388)              // W' rows of 776 halves
#define HA_WORDS (16 * 388)              // one A' parity buffer
#define HA_BYTES (HA_WORDS * 4)
#define PH_FLOATS (12 * 16 * 8)
#define SCAN_SMEM_BYTES ((WP_WORDS + 2 * HA_WORDS + PH_FLOATS) * 4)

__device__ __forceinline__ unsigned smem_u32(const void* p) {
    unsigned r;
    asm("{ .reg .u64 t; cvta.to.shared.u64 t, %1; cvt.u32.u64 %0, t; }"
        : "=r"(r) : "l"(p));
    return r;
}
__device__ __forceinline__ void ldsm_x4(unsigned& r0, unsigned& r1,
                                        unsigned& r2, unsigned& r3, unsigned a) {
    asm volatile("ldmatrix.sync.aligned.m8n8.x4.shared.b16 {%0,%1,%2,%3}, [%4];"
                 : "=r"(r0), "=r"(r1), "=r"(r2), "=r"(r3) : "r"(a));
}
__device__ __forceinline__ void ldsm_x2(unsigned& r0, unsigned& r1, unsigned a) {
    asm volatile("ldmatrix.sync.aligned.m8n8.x2.shared.b16 {%0,%1}, [%2];"
                 : "=r"(r0), "=r"(r1) : "r"(a));
}
__device__ __forceinline__ void mma_bf16(float* c, unsigned a0, unsigned a1,
                                         unsigned a2, unsigned a3,
                                         unsigned b0, unsigned b1) {
    asm volatile("mma.sync.aligned.m16n8k16.row.col.f32.bf16.bf16.f32 "
                 "{%0,%1,%2,%3}, {%4,%5,%6,%7}, {%8,%9}, {%0,%1,%2,%3};"
                 : "+f"(c[0]), "+f"(c[1]), "+f"(c[2]), "+f"(c[3])
                 : "r"(a0), "r"(a1), "r"(a2), "r"(a3), "r"(b0), "r"(b1));
}
__device__ __forceinline__ unsigned packh(float o) {
    __nv_bfloat16 h = __float2bfloat16(o);
    float hf = __bfloat162float(h);
    __nv_bfloat16 lo = __float2bfloat16(o - hf);
    return ((unsigned)__bfloat16_as_ushort(h) << 16) |
           (unsigned)__bfloat16_as_ushort(lo);
}
__device__ __forceinline__ unsigned bfpair(float a, float b) {
    return (unsigned)__bfloat16_as_ushort(__float2bfloat16(a)) |
           ((unsigned)__bfloat16_as_ushort(__float2bfloat16(b)) << 16);
}
__device__ __forceinline__ float gru_cell(float ra, float za, float xn,
                                          float hn, float hp) {
    float r = 1.0f / (1.0f + __expf(-ra));
    float z = 1.0f / (1.0f + __expf(-za));
    float n = tanhf(xn + r * hn);
    return (1.0f - z) * n + z * hp;
}

__global__ __launch_bounds__(256, 1)
void gru_scan_tc(const float* __restrict__ px,     // [2][T][B][768]
                 const float* __restrict__ w_hh,   // [2][768][256]
                 const float* __restrict__ b_hh,   // [2][768]
                 unsigned* __restrict__ hbuf,      // [2 parity][2 dir][B][H] packed
                 unsigned* __restrict__ flags,     // [2 dir][8 bg][8 slot]
                 float* __restrict__ y_out,        // null or [T][B][2H]
                 float* __restrict__ h_last)       // null or [2][B][H]
{
    extern __shared__ __align__(16) unsigned smem_s[];
    unsigned* Wp   = smem_s;                       // [96][388]
    unsigned* hA   = Wp + WP_WORDS;                // [2 parity][16][388]
    float*    ph_s = (float*)(hA + 2 * HA_WORDS);  // [12][16][8]

    const int bg  = blockIdx.x;
    const int sl  = blockIdx.y;
    const int dir = blockIdx.z;
    const int tid = threadIdx.x;
    const int wid = tid >> 5;
    const int l   = tid & 31;
    const int g   = l >> 2;
    const int tg  = l & 3;
    const int wq  = wid & 3;

    // ---- one-time: convert W slice -> B' = [W_hi | W_hi | W_lo] bf16 ----
    const float* wsrc = w_hh + dir * (G3 * H_);
    for (int e = tid; e < 96 * 384; e += 256) {
        int row = e / 384, cw = e - row * 384;
        int kp  = cw * 2;
        int blk = kp >> 8;               // 0,1 -> hi ; 2 -> lo
        int kk  = kp & 255;
        int grow = (row >> 5) * H_ + sl * 32 + (row & 31);
        float w0 = wsrc[grow * H_ + kk], w1 = wsrc[grow * H_ + kk + 1];
        unsigned u;
        if (blk < 2) {
            u = bfpair(w0, w1);
        } else {
            float h0 = __bfloat162float(__float2bfloat16(w0));
            float h1 = __bfloat162float(__float2bfloat16(w1));
            u = bfpair(w0 - h0, w1 - h1);
        }
        Wp[row * 388 + cw] = u;
    }

    // ---- per-lane constants ----
    const int u0 = wq * 8 + 2 * tg;      // local unit (even), gate warps
    const int ug = sl * 32 + u0;
    float br0 = 0, br1 = 0, bz0 = 0, bz1 = 0, bn0 = 0, bn1 = 0;
    if (wid < 4) {
        const float* bb = b_hh + dir * G3;
        br0 = bb[ug];            br1 = bb[ug + 1];
        bz0 = bb[H_ + ug];       bz1 = bb[H_ + ug + 1];
        bn0 = bb[2 * H_ + ug];   bn1 = bb[2 * H_ + ug + 1];
    }

    const unsigned AW = smem_u32(Wp);
    const unsigned AA = smem_u32(hA);
    const unsigned preA = AA + (((l >> 3) & 1) * 8 + (l & 7)) * 1552
                             + ((l >> 4) & 1) * 16;
    unsigned preB[3];
#pragma unroll
    for (int gi = 0; gi < 3; gi++)
        preB[gi] = AW + (gi * 32 + wq * 8 + (l & 7)) * 1552
                      + ((l >> 3) & 1) * 16;
    const unsigned kb0 = (wid < 4) ? 0u : 768u;   // byte offset of K'-half

    unsigned* slots = flags + (dir * 8 + bg) * 8; // 8 u32 = one 32B sector
    __syncthreads();                      // W' ready

    // ---- one-time: B' fragments into registers; zero both A' buffers ----
    unsigned Breg[3][24][2];
#pragma unroll
    for (int ks = 0; ks < 24; ks++) {
        unsigned koff = kb0 + ks * 32;
#pragma unroll
        for (int gi = 0; gi < 3; gi++)
            ldsm_x2(Breg[gi][ks][0], Breg[gi][ks][1], preB[gi] + koff);
    }
    for (int e = tid; e < 2 * HA_WORDS; e += 256) hA[e] = 0u;

    // px prefetch for step 0 (gate warps)
    float2 pr0, pz0, pn0, pr1, pz1, pn1;
    if (wid < 4) {
        int t0 = dir ? (T_ - 1) : 0;
        const float* p0 = px + ((size_t)(dir * T_ + t0) * B_ + bg * 16 + g) * G3 + ug;
        const float* p1 = p0 + 8 * G3;
        pr0 = *(const float2*)(p0);
        pz0 = *(const float2*)(p0 + H_);
        pn0 = *(const float2*)(p0 + 2 * H_);
        pr1 = *(const float2*)(p1);
        pz1 = *(const float2*)(p1 + H_);
        pn1 = *(const float2*)(p1 + 2 * H_);
    }
    __syncthreads();                      // A'[0] zeros visible

    for (int step = 0; step < T_; step++) {
        const int t   = dir ? (T_ - 1 - step) : step;
        const int par = step & 1;
        unsigned* hdst = hbuf + (((par ^ 1) * 2) + dir) * (B_ * H_);

        // ---- MMA over this warp's K'-half on A'[par] (B in registers) ----
        float acc[3][4];
#pragma unroll
        for (int gi = 0; gi < 3; gi++)
#pragma unroll
            for (int j = 0; j < 4; j++) acc[gi][j] = 0.0f;

        const unsigned pA = preA + par * HA_BYTES;
#pragma unroll
        for (int ks = 0; ks < 24; ks++) {
            unsigned a0, a1, a2, a3;
            ldsm_x4(a0, a1, a2, a3, pA + kb0 + ks * 32);
#pragma unroll
            for (int gi = 0; gi < 3; gi++)
                mma_bf16(acc[gi], a0, a1, a2, a3,
                         Breg[gi][ks][0], Breg[gi][ks][1]);
        }

        // ---- warps 4-7 publish partials ----
        if (wid >= 4) {
            int wb = (wid - 4) * 3;
#pragma unroll
            for (int gi = 0; gi < 3; gi++) {
                *(float2*)&ph_s[((wb + gi) * 16 + g) * 8 + 2 * tg] =
                    make_float2(acc[gi][0], acc[gi][1]);
                *(float2*)&ph_s[((wb + gi) * 16 + g + 8) * 8 + 2 * tg] =
                    make_float2(acc[gi][2], acc[gi][3]);
            }
        }
        __syncthreads();                  // partials visible

        if (wid < 4) {
            // ---- gate warps: combine, gates, publish h, release ----
            int wb = wid * 3;
#pragma unroll
            for (int gi = 0; gi < 3; gi++) {
                float2 p0 = *(const float2*)&ph_s[((wb + gi) * 16 + g) * 8 + 2 * tg];
                float2 p1 = *(const float2*)&ph_s[((wb + gi) * 16 + g + 8) * 8 + 2 * tg];
                acc[gi][0] += p0.x; acc[gi][1] += p0.y;
                acc[gi][2] += p1.x; acc[gi][3] += p1.y;
            }

            // hp from A'[par] hi+lo words of own unit pair
            const int wd = par * HA_WORDS + sl * 16 + wq * 4 + tg;
            unsigned wh0 = hA[g * 388 + wd],       wl0 = hA[g * 388 + wd + 128];
            unsigned wh1 = hA[(g + 8) * 388 + wd], wl1 = hA[(g + 8) * 388 + wd + 128];
            float hp00 = __uint_as_float(wh0 << 16) + __uint_as_float(wl0 << 16);
            float hp01 = __uint_as_float(wh0 & 0xffff0000u) +
                         __uint_as_float(wl0 & 0xffff0000u);
            float hp10 = __uint_as_float(wh1 << 16) + __uint_as_float(wl1 << 16);
            float hp11 = __uint_as_float(wh1 & 0xffff0000u) +
                         __uint_as_float(wl1 & 0xffff0000u);

            float o00 = gru_cell(pr0.x + acc[0][0] + br0, pz0.x + acc[1][0] + bz0,
                                 pn0.x, acc[2][0] + bn0, hp00);
            float o01 = gru_cell(pr0.y + acc[0][1] + br1, pz0.y + acc[1][1] + bz1,
                                 pn0.y, acc[2][1] + bn1, hp01);
            float o10 = gru_cell(pr1.x + acc[0][2] + br0, pz1.x + acc[1][2] + bz0,
                                 pn1.x, acc[2][2] + bn0, hp10);
            float o11 = gru_cell(pr1.y + acc[0][3] + br1, pz1.y + acc[1][3] + bz1,
                                 pn1.y, acc[2][3] + bn1, hp11);

            int b0g = bg * 16 + g, b1g = b0g + 8;
            unsigned pk00 = packh(o00), pk01 = packh(o01);
            unsigned pk10 = packh(o10), pk11 = packh(o11);
            asm volatile("st.global.cg.v2.u32 [%0], {%1,%2};"
                         :: "l"(&hdst[b0g * H_ + ug]), "r"(pk00), "r"(pk01) : "memory");
            asm volatile("st.global.cg.v2.u32 [%0], {%1,%2};"
                         :: "l"(&hdst[b1g * H_ + ug]), "r"(pk10), "r"(pk11) : "memory");

            // order all gate-warp h stores, then release our slot
            asm volatile("bar.sync 1, 128;" ::: "memory");
            if (tid == 0)
                asm volatile("st.release.gpu.global.u32 [%0], %1;"
                             :: "l"(slots + sl), "r"((unsigned)(step + 1)) : "memory");

            if (y_out) {
                *(float2*)&y_out[((size_t)t * B_ + b0g) * (2 * H_) + dir * H_ + ug] =
                    make_float2(o00, o01);
                *(float2*)&y_out[((size_t)t * B_ + b1g) * (2 * H_) + dir * H_ + ug] =
                    make_float2(o10, o11);
            }
            if (h_last && step == T_ - 1) {
                *(float2*)&h_last[(dir * B_ + b0g) * H_ + ug] = make_float2(o00, o01);
                *(float2*)&h_last[(dir * B_ + b1g) * H_ + ug] = make_float2(o10, o11);
            }

            // prefetch px for next step
            if (step + 1 < T_) {
                int tn = dir ? (T_ - 2 - step) : (step + 1);
                const float* p0 = px + ((size_t)(dir * T_ + tn) * B_ + bg * 16 + g) * G3 + ug;
                const float* p1 = p0 + 8 * G3;
                pr0 = *(const float2*)(p0);
                pz0 = *(const float2*)(p0 + H_);
                pn0 = *(const float2*)(p0 + 2 * H_);
                pr1 = *(const float2*)(p1);
                pz1 = *(const float2*)(p1 + H_);
                pn1 = *(const float2*)(p1 + 2 * H_);
            }
        } else if (step + 1 < T_) {
            // ---- warps 4-7: poll all 8 slots, then stage A'[par^1] ----
            if (wid == 4) {
                const unsigned* f = slots + (l & 7);
                unsigned v;
                do {
                    asm volatile("ld.acquire.gpu.global.u32 %0, [%1];"
                                 : "=r"(v) : "l"(f) : "memory");
                } while (__any_sync(0xffffffffu, v < (unsigned)(step + 1)));
            }
            asm volatile("bar.sync 2, 128;" ::: "memory");

            const int gt = tid - 128;
            const int b  = gt >> 3;          // 0..15
            const int kc = (gt & 7) * 32;    // unit chunk (32 units = 128B)
            const unsigned* src = &hdst[(bg * 16 + b) * H_ + kc];
            uint4 q[8];
#pragma unroll
            for (int j = 0; j < 8; j++)
                q[j] = __ldcg((const uint4*)(src + j * 4));
            unsigned w[32];
#pragma unroll
            for (int j = 0; j < 8; j++) {
                w[4 * j]     = q[j].x; w[4 * j + 1] = q[j].y;
                w[4 * j + 2] = q[j].z; w[4 * j + 3] = q[j].w;
            }
            unsigned hp_[16], lp_[16];
#pragma unroll
            for (int j = 0; j < 16; j++) {
                hp_[j] = __byte_perm(w[2 * j], w[2 * j + 1], 0x7632);
                lp_[j] = __byte_perm(w[2 * j], w[2 * j + 1], 0x5410);
            }
            unsigned base = (par ^ 1) * HA_WORDS + b * 388 + (kc >> 1);
#pragma unroll
            for (int j = 0; j < 4; j++) {
                *(uint4*)&hA[base + j * 4] =
                    make_uint4(hp_[4 * j], hp_[4 * j + 1], hp_[4 * j + 2], hp_[4 * j + 3]);
                *(uint4*)&hA[base + 128 + j * 4] =
                    make_uint4(lp_[4 * j], lp_[4 * j + 1], lp_[4 * j + 2], lp_[4 * j + 3]);
                *(uint4*)&hA[base + 256 + j * 4] =
                    make_uint4(hp_[4 * j], hp_[4 * j + 1], hp_[4 * j + 2], hp_[4 * j + 3]);
            }
        }

        __syncthreads();   // A'[par^1] staged; gate tail done; ph_s reusable
    }
}

// ---------------------------------------------------------------------------
// Output head
// ---------------------------------------------------------------------------
__global__ void head_kernel(const float* __restrict__ hlast,
                            const float* __restrict__ w_out,
                            const float* __restrict__ b_out,
                            float* __restrict__ out)
{
    int id = blockIdx.x * blockDim.x + threadIdx.x;
    if (id >= B_ * NOUT) return;
    int b = id >> 2, o = id & 3;
    const float* hf = hlast + b * H_;
    const float* hb = hlast + (B_ + b) * H_;
    const float* wo = w_out + o * (2 * H_);
    float s = b_out[o];
#pragma unroll 8
    for (int j = 0; j < H_; j++) s += hf[j] * wo[j];
#pragma unroll 8
    for (int j = 0; j < H_; j++) s += hb[j] * wo[H_ + j];
    out[id] = s;
}

// ---------------------------------------------------------------------------
// Launch
// ---------------------------------------------------------------------------
extern "C" void kernel_launch(void* const* d_in, const int* in_sizes, int n_in,
                              void* d_out, int out_size)
{
    const float* data  = (const float*)d_in[0];
    const float* w_ih0 = (const float*)d_in[1];
    const float* w_hh0 = (const float*)d_in[2];
    const float* b_ih0 = (const float*)d_in[3];
    const float* b_hh0 = (const float*)d_in[4];
    const float* w_ih1 = (const float*)d_in[5];
    const float* w_hh1 = (const float*)d_in[6];
    const float* b_ih1 = (const float*)d_in[7];
    const float* b_hh1 = (const float*)d_in[8];
    const float* w_out = (const float*)d_in[9];
    const float* b_out = (const float*)d_in[10];
    float* out = (float*)d_out;

    float *px0, *px1, *y0, *hlast; unsigned *h, *fl;
    cudaGetSymbolAddress((void**)&px0,   g_px0);
    cudaGetSymbolAddress((void**)&px1,   g_px1);
    cudaGetSymbolAddress((void**)&y0,    g_y0);
    cudaGetSymbolAddress((void**)&h,     g_h);
    cudaGetSymbolAddress((void**)&hlast, g_hlast);
    cudaGetSymbolAddress((void**)&fl,    g_flags);

    cudaFuncSetAttribute(gemm_proj_tc, cudaFuncAttributeMaxDynamicSharedMemorySize,
                         TC_SMEM);
    cudaFuncSetAttribute(gru_scan_tc, cudaFuncAttributeMaxDynamicSharedMemorySize,
                         SCAN_SMEM_BYTES);

    zero_kernel<<<256, 256>>>();

    // Layer 0 input projection: M = B*T = 131072, K = 128
    dim3 gtc(1536 / 128, 131072 / 128);
    gemm_proj_tc<<<gtc, 256, TC_SMEM>>>(data, w_ih0, b_ih0, px0, IN_, 0);

    // Layer 0 bidirectional scan (writes y0)
    dim3 gs(8, 8, 2);
    const int hLayerStride = 2 * 2 * B_ * H_;
    const int fLayerStride = 2 * 8 * 8;
    gru_scan_tc<<<gs, 256, SCAN_SMEM_BYTES>>>(px0, w_hh0, b_hh0,
                                              h, fl, y0, nullptr);

    // Layer 1 input projection: M = T*B = 131072, K = 512
    gemm_proj_tc<<<gtc, 256, TC_SMEM>>>(y0, w_ih1, b_ih1, px1, 2 * H_, 1);

    // Layer 1 bidirectional scan (writes h_last only)
    gru_scan_tc<<<gs, 256, SCAN_SMEM_BYTES>>>(px1, w_hh1, b_hh1,
                                              h + hLayerStride, fl + fLayerStride,
                                              nullptr, hlast);

    // Output head
    head_kernel<<<2, 256>>>(hlast, w_out, b_out, out);
}

// round 15
// speedup vs baseline: 1.4964x; 1.4964x over previous
#include <cuda_runtime.h>
#include <cuda_bf16.h>
#include <cstdint>

#define B_   128
#define T_   1024
#define IN_  128
#define H_   256
#define G3   768          // 3*H
#define NOUT 4

// ---------------------------------------------------------------------------
// Static device scratch (no cudaMalloc allowed).
// ---------------------------------------------------------------------------
__device__ float    g_px0[2 * T_ * B_ * G3];
__device__ float    g_px1[2 * T_ * B_ * G3];
__device__ float    g_y0 [T_ * B_ * 2 * H_];
__device__ unsigned g_h  [2 * 2 * 2 * B_ * H_];    // packed (bf16hi|bf16lo) h
__device__ float    g_hlast[2 * B_ * H_];
__device__ unsigned g_flags[2 * 2 * 8 * T_];       // [layer][dir][bg][step]

__global__ void zero_kernel() {
    const int n1 = 2 * 2 * 2 * B_ * H_;
    const int n2 = 2 * 2 * 8 * T_;
    int stride = gridDim.x * blockDim.x;
    for (int i = blockIdx.x * blockDim.x + threadIdx.x; i < n1; i += stride)
        g_h[i] = 0u;
    for (int i = blockIdx.x * blockDim.x + threadIdx.x; i < n2; i += stride)
        g_flags[i] = 0u;
}

// ---------------------------------------------------------------------------
// Tensor-core projection GEMM (3xTF32 split). Unchanged.
// ---------------------------------------------------------------------------
#define TC_SMEM (4 * 128 * 36 * 4)

__device__ __forceinline__ unsigned f2tf(float x) {
    unsigned r; asm("cvt.rna.tf32.f32 %0, %1;" : "=r"(r) : "f"(x)); return r;
}

__device__ __forceinline__ void mma_tf32(float* c, const unsigned* a, const unsigned* b) {
    asm volatile("mma.sync.aligned.m16n8k8.row.col.f32.tf32.tf32.f32 "
                 "{%0,%1,%2,%3}, {%4,%5,%6,%7}, {%8,%9}, {%0,%1,%2,%3};"
                 : "+f"(c[0]), "+f"(c[1]), "+f"(c[2]), "+f"(c[3])
                 : "r"(a[0]), "r"(a[1]), "r"(a[2]), "r"(a[3]),
                   "r"(b[0]), "r"(b[1]));
}

__device__ __forceinline__ void px_scatter(float v, int m, int n, int mode,
                                           const float* __restrict__ bias,
                                           float* __restrict__ out) {
    int t, b;
    if (mode == 0) { b = m >> 10; t = m & (T_ - 1); }
    else           { t = m >> 7;  b = m & (B_ - 1); }
    int dir = (n >= G3) ? 1 : 0;
    int g   = n - dir * G3;
    out[((size_t)(dir * T_ + t) * B_ + b) * G3 + g] = v + __ldg(&bias[n]);
}

__global__ __launch_bounds__(256, 1)
void gemm_proj_tc(const float* __restrict__ A, const float* __restrict__ W,
                  const float* __restrict__ bias, float* __restrict__ out,
                  int K, int mode)
{
    extern __shared__ unsigned sm_u[];
    unsigned* Ah = sm_u;
    unsigned* Al = Ah + 128 * 36;
    unsigned* Bh = Al + 128 * 36;
    unsigned* Bl = Bh + 128 * 36;

    const int tid  = threadIdx.x;
    const int n0   = blockIdx.x * 128;
    const int m0   = blockIdx.y * 128;
    const int wid  = tid >> 5;
    const int lane = tid & 31;
    const int wm   = (wid & 3) * 32;
    const int wn   = (wid >> 2) * 64;
    const int g    = lane >> 2;
    const int tg   = lane & 3;

    float acc[2][8][4];
#pragma unroll
    for (int mt = 0; mt < 2; mt++)
#pragma unroll
        for (int nt = 0; nt < 8; nt++)
#pragma unroll
            for (int j = 0; j < 4; j++) acc[mt][nt][j] = 0.0f;

    for (int k0 = 0; k0 < K; k0 += 32) {
#pragma unroll
        for (int i = 0; i < 4; i++) {
            int e = tid + i * 256;
            int r = e >> 3;
            int c = (e & 7) * 4;

            float4 va = *(const float4*)&A[(size_t)(m0 + r) * K + k0 + c];
            unsigned h0 = f2tf(va.x), h1 = f2tf(va.y),
                     h2 = f2tf(va.z), h3 = f2tf(va.w);
            *(uint4*)&Ah[r * 36 + c] = make_uint4(h0, h1, h2, h3);
            *(uint4*)&Al[r * 36 + c] = make_uint4(
                f2tf(va.x - __uint_as_float(h0)),
                f2tf(va.y - __uint_as_float(h1)),
                f2tf(va.z - __uint_as_float(h2)),
                f2tf(va.w - __uint_as_float(h3)));

            float4 vb = *(const float4*)&W[(size_t)(n0 + r) * K + k0 + c];
            unsigned p0 = f2tf(vb.x), p1 = f2tf(vb.y),
                     p2 = f2tf(vb.z), p3 = f2tf(vb.w);
            *(uint4*)&Bh[r * 36 + c] = make_uint4(p0, p1, p2, p3);
            *(uint4*)&Bl[r * 36 + c] = make_uint4(
                f2tf(vb.x - __uint_as_float(p0)),
                f2tf(vb.y - __uint_as_float(p1)),
                f2tf(vb.z - __uint_as_float(p2)),
                f2tf(vb.w - __uint_as_float(p3)));
        }
        __syncthreads();

#pragma unroll
        for (int kk = 0; kk < 4; kk++) {
            const int kc = kk * 8 + tg;
            unsigned ah[2][4], al[2][4], bh[8][2], bl[8][2];
#pragma unroll
            for (int mt = 0; mt < 2; mt++) {
                int m = wm + mt * 16;
                ah[mt][0] = Ah[(m + g) * 36 + kc];
                ah[mt][1] = Ah[(m + 8 + g) * 36 + kc];
                ah[mt][2] = Ah[(m + g) * 36 + kc + 4];
                ah[mt][3] = Ah[(m + 8 + g) * 36 + kc + 4];
                al[mt][0] = Al[(m + g) * 36 + kc];
                al[mt][1] = Al[(m + 8 + g) * 36 + kc];
                al[mt][2] = Al[(m + g) * 36 + kc + 4];
                al[mt][3] = Al[(m + 8 + g) * 36 + kc + 4];
            }
#pragma unroll
            for (int nt = 0; nt < 8; nt++) {
                int n = wn + nt * 8;
                bh[nt][0] = Bh[(n + g) * 36 + kc];
                bh[nt][1] = Bh[(n + g) * 36 + kc + 4];
                bl[nt][0] = Bl[(n + g) * 36 + kc];
                bl[nt][1] = Bl[(n + g) * 36 + kc + 4];
            }
#pragma unroll
            for (int mt = 0; mt < 2; mt++)
#pragma unroll
                for (int nt = 0; nt < 8; nt++) {
                    mma_tf32(acc[mt][nt], ah[mt], bh[nt]);
                    mma_tf32(acc[mt][nt], ah[mt], bl[nt]);
                    mma_tf32(acc[mt][nt], al[mt], bh[nt]);
                }
        }
        __syncthreads();
    }

#pragma unroll
    for (int mt = 0; mt < 2; mt++) {
#pragma unroll
        for (int nt = 0; nt < 8; nt++) {
            int m = m0 + wm + mt * 16 + g;
            int n = n0 + wn + nt * 8 + tg * 2;
            px_scatter(acc[mt][nt][0], m,     n,     mode, bias, out);
            px_scatter(acc[mt][nt][1], m,     n + 1, mode, bias, out);
            px_scatter(acc[mt][nt][2], m + 8, n,     mode, bias, out);
            px_scatter(acc[mt][nt][3], m + 8, n + 1, mode, bias, out);
        }
    }
}

// ---------------------------------------------------------------------------
// Tensor-core GRU scan (bf16 hi/lo K-concat) — R12 skeleton with ONE change:
// the flag release is ordered by a gate-warp-only named barrier (bar.sync 1,
// 128) instead of a full __syncthreads, fires BEFORE y_out/h_last/prefetch,
// and the trailing full barrier is deleted (loop-top spin barrier provides
// the WAR protection for hA/hraw/ph_s reuse).
// Grid (8 bg, 8 slice, 2 dir) = 128 CTAs, 256 threads, 1 CTA/SM.
// ---------------------------------------------------------------------------
#define WP_WORDS   (96 * 388)            // W' rows of 776 halves (u32 words)
#define HA_WORDS   (16 * 388)            // A' rows of 776 halves
#define HRAW_WORDS (16 * 260)            // raw packed h, padded rows
#define PH_FLOATS  (12 * 16 * 8)         // partial sums
#define SCAN_SMEM_BYTES ((WP_WORDS + HA_WORDS + HRAW_WORDS + PH_FLOATS) * 4)

__device__ __forceinline__ unsigned smem_u32(const void* p) {
    unsigned r;
    asm("{ .reg .u64 t; cvta.to.shared.u64 t, %1; cvt.u32.u64 %0, t; }"
        : "=r"(r) : "l"(p));
    return r;
}
__device__ __forceinline__ void ldsm_x4(unsigned& r0, unsigned& r1,
                                        unsigned& r2, unsigned& r3, unsigned a) {
    asm volatile("ldmatrix.sync.aligned.m8n8.x4.shared.b16 {%0,%1,%2,%3}, [%4];"
                 : "=r"(r0), "=r"(r1), "=r"(r2), "=r"(r3) : "r"(a));
}
__device__ __forceinline__ void ldsm_x2(unsigned& r0, unsigned& r1, unsigned a) {
    asm volatile("ldmatrix.sync.aligned.m8n8.x2.shared.b16 {%0,%1}, [%2];"
                 : "=r"(r0), "=r"(r1) : "r"(a));
}
__device__ __forceinline__ void mma_bf16(float* c, unsigned a0, unsigned a1,
                                         unsigned a2, unsigned a3,
                                         unsigned b0, unsigned b1) {
    asm volatile("mma.sync.aligned.m16n8k16.row.col.f32.bf16.bf16.f32 "
                 "{%0,%1,%2,%3}, {%4,%5,%6,%7}, {%8,%9}, {%0,%1,%2,%3};"
                 : "+f"(c[0]), "+f"(c[1]), "+f"(c[2]), "+f"(c[3])
                 : "r"(a0), "r"(a1), "r"(a2), "r"(a3), "r"(b0), "r"(b1));
}
__device__ __forceinline__ unsigned packh(float o) {
    __nv_bfloat16 h = __float2bfloat16(o);
    float hf = __bfloat162float(h);
    __nv_bfloat16 lo = __float2bfloat16(o - hf);
    return ((unsigned)__bfloat16_as_ushort(h) << 16) |
           (unsigned)__bfloat16_as_ushort(lo);
}
__device__ __forceinline__ float unpackh(unsigned v) {
    return __uint_as_float(v & 0xffff0000u) + __uint_as_float(v << 16);
}
__device__ __forceinline__ unsigned bfpair(float a, float b) {
    return (unsigned)__bfloat16_as_ushort(__float2bfloat16(a)) |
           ((unsigned)__bfloat16_as_ushort(__float2bfloat16(b)) << 16);
}
__device__ __forceinline__ float gru_cell(float ra, float za, float xn,
                                          float hn, float hp) {
    float r = 1.0f / (1.0f + __expf(-ra));
    float z = 1.0f / (1.0f + __expf(-za));
    float n = tanhf(xn + r * hn);
    return (1.0f - z) * n + z * hp;
}

__global__ __launch_bounds__(256, 1)
void gru_scan_tc(const float* __restrict__ px,     // [2][T][B][768]
                 const float* __restrict__ w_hh,   // [2][768][256]
                 const float* __restrict__ b_hh,   // [2][768]
                 unsigned* __restrict__ hbuf,      // [2 parity][2 dir][B][H] packed
                 unsigned* __restrict__ flags,     // [2 dir][8 bg][T]
                 float* __restrict__ y_out,        // null or [T][B][2H]
                 float* __restrict__ h_last)       // null or [2][B][H]
{
    extern __shared__ __align__(16) unsigned smem_s[];
    unsigned* Wp   = smem_s;               // [96][388]
    unsigned* hA   = Wp + WP_WORDS;        // [16][388]
    unsigned* hraw = hA + HA_WORDS;        // [16][260]
    float*    ph_s = (float*)(hraw + HRAW_WORDS);   // [12][16][8]

    const int bg  = blockIdx.x;
    const int sl  = blockIdx.y;
    const int dir = blockIdx.z;
    const int tid = threadIdx.x;
    const int wid = tid >> 5;
    const int l   = tid & 31;
    const int g   = l >> 2;
    const int tg  = l & 3;
    const int wq  = wid & 3;

    // ---- one-time: convert W slice -> B' = [W_hi | W_hi | W_lo] bf16 ----
    const float* wsrc = w_hh + dir * (G3 * H_);
    for (int e = tid; e < 96 * 384; e += 256) {
        int row = e / 384, cw = e - row * 384;
        int kp  = cw * 2;
        int blk = kp >> 8;               // 0,1 -> hi ; 2 -> lo
        int kk  = kp & 255;
        int grow = (row >> 5) * H_ + sl * 32 + (row & 31);
        float w0 = wsrc[grow * H_ + kk], w1 = wsrc[grow * H_ + kk + 1];
        unsigned u;
        if (blk < 2) {
            u = bfpair(w0, w1);
        } else {
            float h0 = __bfloat162float(__float2bfloat16(w0));
            float h1 = __bfloat162float(__float2bfloat16(w1));
            u = bfpair(w0 - h0, w1 - h1);
        }
        Wp[row * 388 + cw] = u;
    }

    // ---- per-lane constants ----
    const int u0 = wq * 8 + 2 * tg;      // local unit (even), gate warps
    const int ug = sl * 32 + u0;
    float br0 = 0, br1 = 0, bz0 = 0, bz1 = 0, bn0 = 0, bn1 = 0;
    if (wid < 4) {
        const float* bb = b_hh + dir * G3;
        br0 = bb[ug];            br1 = bb[ug + 1];
        bz0 = bb[H_ + ug];       bz1 = bb[H_ + ug + 1];
        bn0 = bb[2 * H_ + ug];   bn1 = bb[2 * H_ + ug + 1];
    }

    const unsigned AW = smem_u32(Wp);
    const unsigned AA = smem_u32(hA);
    const unsigned preA = AA + (((l >> 3) & 1) * 8 + (l & 7)) * 1552
                             + ((l >> 4) & 1) * 16;
    unsigned preB[3];
#pragma unroll
    for (int gi = 0; gi < 3; gi++)
        preB[gi] = AW + (gi * 32 + wq * 8 + (l & 7)) * 1552
                      + ((l >> 3) & 1) * 16;
    const unsigned kb0 = (wid < 4) ? 0u : 768u;   // byte offset of K'-half

    unsigned* flg = flags + (dir * 8 + bg) * T_;
    __syncthreads();                      // W' ready

    // ---- one-time: load this warp's B' fragments into registers ----
    unsigned Breg[3][24][2];
#pragma unroll
    for (int ks = 0; ks < 24; ks++) {
        unsigned koff = kb0 + ks * 32;
#pragma unroll
        for (int gi = 0; gi < 3; gi++)
            ldsm_x2(Breg[gi][ks][0], Breg[gi][ks][1], preB[gi] + koff);
    }

    // px prefetch for step 0 (gate warps)
    float2 pr0, pz0, pn0, pr1, pz1, pn1;
    if (wid < 4) {
        int t0 = dir ? (T_ - 1) : 0;
        const float* p0 = px + ((size_t)(dir * T_ + t0) * B_ + bg * 16 + g) * G3 + ug;
        const float* p1 = p0 + 8 * G3;
        pr0 = *(const float2*)(p0);
        pz0 = *(const float2*)(p0 + H_);
        pn0 = *(const float2*)(p0 + 2 * H_);
        pr1 = *(const float2*)(p1);
        pz1 = *(const float2*)(p1 + H_);
        pn1 = *(const float2*)(p1 + 2 * H_);
    }

    for (int step = 0; step < T_; step++) {
        const int t = dir ? (T_ - 1 - step) : step;
        const unsigned* hsrc = hbuf + ((step & 1) * 2 + dir) * (B_ * H_);
        unsigned*       hdst = hbuf + ((((step + 1) & 1) * 2) + dir) * (B_ * H_);

        // ---- wait for all 8 slice-CTAs' h of previous step ----
        // (this barrier also WAR-protects hA/hraw/ph_s reuse below)
        if (step) {
            if (tid == 0) {
                const unsigned* f = flg + step - 1;
                unsigned v;
                do {
                    asm volatile("ld.acquire.gpu.global.u32 %0, [%1];"
                                 : "=r"(v) : "l"(f) : "memory");
                } while (v < 8u);
            }
            __syncthreads();
        }

        // ---- stage h: packed u32 -> A' (hi|lo|hi) + raw copy ----
        {
            const int b  = tid >> 4;
            const int kc = (tid & 15) * 16;
            const uint4* src = (const uint4*)&hsrc[(bg * 16 + b) * H_ + kc];
            uint4 q0 = __ldcg(src + 0), q1 = __ldcg(src + 1),
                  q2 = __ldcg(src + 2), q3 = __ldcg(src + 3);
            unsigned w[16] = {q0.x, q0.y, q0.z, q0.w, q1.x, q1.y, q1.z, q1.w,
                              q2.x, q2.y, q2.z, q2.w, q3.x, q3.y, q3.z, q3.w};
            unsigned hp_[8], lp_[8];
#pragma unroll
            for (int j = 0; j < 8; j++) {
                hp_[j] = __byte_perm(w[2 * j], w[2 * j + 1], 0x7632);
                lp_[j] = __byte_perm(w[2 * j], w[2 * j + 1], 0x5410);
            }
            unsigned base = b * 388 + (kc >> 1);
            *(uint4*)&hA[base]       = make_uint4(hp_[0], hp_[1], hp_[2], hp_[3]);
            *(uint4*)&hA[base + 4]   = make_uint4(hp_[4], hp_[5], hp_[6], hp_[7]);
            *(uint4*)&hA[base + 128] = make_uint4(lp_[0], lp_[1], lp_[2], lp_[3]);
            *(uint4*)&hA[base + 132] = make_uint4(lp_[4], lp_[5], lp_[6], lp_[7]);
            *(uint4*)&hA[base + 256] = make_uint4(hp_[0], hp_[1], hp_[2], hp_[3]);
            *(uint4*)&hA[base + 260] = make_uint4(hp_[4], hp_[5], hp_[6], hp_[7]);
            uint4* rw = (uint4*)&hraw[b * 260 + kc];
            rw[0] = q0; rw[1] = q1; rw[2] = q2; rw[3] = q3;
        }
        __syncthreads();

        // ---- MMA over this warp's K'-half (B from registers) ----
        float acc[3][4];
#pragma unroll
        for (int gi = 0; gi < 3; gi++)
#pragma unroll
            for (int j = 0; j < 4; j++) acc[gi][j] = 0.0f;

#pragma unroll
        for (int ks = 0; ks < 24; ks++) {
            unsigned koff = kb0 + ks * 32;
            unsigned a0, a1, a2, a3;
            ldsm_x4(a0, a1, a2, a3, preA + koff);
#pragma unroll
            for (int gi = 0; gi < 3; gi++)
                mma_bf16(acc[gi], a0, a1, a2, a3,
                         Breg[gi][ks][0], Breg[gi][ks][1]);
        }

        // ---- warps 4-7 publish partials ----
        if (wid >= 4) {
            int wb = (wid - 4) * 3;
#pragma unroll
            for (int gi = 0; gi < 3; gi++) {
                *(float2*)&ph_s[((wb + gi) * 16 + g) * 8 + 2 * tg] =
                    make_float2(acc[gi][0], acc[gi][1]);
                *(float2*)&ph_s[((wb + gi) * 16 + g + 8) * 8 + 2 * tg] =
                    make_float2(acc[gi][2], acc[gi][3]);
            }
        }
        __syncthreads();

        // ---- warps 0-3: combine, gates, publish h, EARLY release ----
        if (wid < 4) {
            int wb = wid * 3;
#pragma unroll
            for (int gi = 0; gi < 3; gi++) {
                float2 p0 = *(const float2*)&ph_s[((wb + gi) * 16 + g) * 8 + 2 * tg];
                float2 p1 = *(const float2*)&ph_s[((wb + gi) * 16 + g + 8) * 8 + 2 * tg];
                acc[gi][0] += p0.x; acc[gi][1] += p0.y;
                acc[gi][2] += p1.x; acc[gi][3] += p1.y;
            }

            uint2 hpa = *(const uint2*)&hraw[g * 260 + ug];
            uint2 hpb = *(const uint2*)&hraw[(g + 8) * 260 + ug];
            float hp00 = unpackh(hpa.x), hp01 = unpackh(hpa.y);
            float hp10 = unpackh(hpb.x), hp11 = unpackh(hpb.y);

            float o00 = gru_cell(pr0.x + acc[0][0] + br0, pz0.x + acc[1][0] + bz0,
                                 pn0.x, acc[2][0] + bn0, hp00);
            float o01 = gru_cell(pr0.y + acc[0][1] + br1, pz0.y + acc[1][1] + bz1,
                                 pn0.y, acc[2][1] + bn1, hp01);
            float o10 = gru_cell(pr1.x + acc[0][2] + br0, pz1.x + acc[1][2] + bz0,
                                 pn1.x, acc[2][2] + bn0, hp10);
            float o11 = gru_cell(pr1.y + acc[0][3] + br1, pz1.y + acc[1][3] + bz1,
                                 pn1.y, acc[2][3] + bn1, hp11);

            int b0g = bg * 16 + g, b1g = b0g + 8;
            unsigned pk00 = packh(o00), pk01 = packh(o01);
            unsigned pk10 = packh(o10), pk11 = packh(o11);
            asm volatile("st.global.cg.v2.u32 [%0], {%1,%2};"
                         :: "l"(&hdst[b0g * H_ + ug]), "r"(pk00), "r"(pk01) : "memory");
            asm volatile("st.global.cg.v2.u32 [%0], {%1,%2};"
                         :: "l"(&hdst[b1g * H_ + ug]), "r"(pk10), "r"(pk11) : "memory");

            // order gate-warp h stores only, then release (off the y_out path)
            asm volatile("bar.sync 1, 128;" ::: "memory");
            if (tid == 0) {
                unsigned* f = flg + step;
                asm volatile("red.release.gpu.global.add.u32 [%0], %1;"
                             :: "l"(f), "r"(1u) : "memory");
            }

            if (y_out) {
                *(float2*)&y_out[((size_t)t * B_ + b0g) * (2 * H_) + dir * H_ + ug] =
                    make_float2(o00, o01);
                *(float2*)&y_out[((size_t)t * B_ + b1g) * (2 * H_) + dir * H_ + ug] =
                    make_float2(o10, o11);
            }
            if (h_last && step == T_ - 1) {
                *(float2*)&h_last[(dir * B_ + b0g) * H_ + ug] = make_float2(o00, o01);
                *(float2*)&h_last[(dir * B_ + b1g) * H_ + ug] = make_float2(o10, o11);
            }

            // prefetch px for next step (overlaps spin + stage + MMA)
            if (step + 1 < T_) {
                int tn = dir ? (T_ - 2 - step) : (step + 1);
                const float* p0 = px + ((size_t)(dir * T_ + tn) * B_ + bg * 16 + g) * G3 + ug;
                const float* p1 = p0 + 8 * G3;
                pr0 = *(const float2*)(p0);
                pz0 = *(const float2*)(p0 + H_);
                pn0 = *(const float2*)(p0 + 2 * H_);
                pr1 = *(const float2*)(p1);
                pz1 = *(const float2*)(p1 + H_);
                pn1 = *(const float2*)(p1 + 2 * H_);
            }
        }
        // no trailing barrier: the loop-top spin __syncthreads WAR-protects
        // hA/hraw/ph_s before the next stage/MMA writes them.
    }
}

// ---------------------------------------------------------------------------
// Output head
// ---------------------------------------------------------------------------
__global__ void head_kernel(const float* __restrict__ hlast,
                            const float* __restrict__ w_out,
                            const float* __restrict__ b_out,
                            float* __restrict__ out)
{
    int id = blockIdx.x * blockDim.x + threadIdx.x;
    if (id >= B_ * NOUT) return;
    int b = id >> 2, o = id & 3;
    const float* hf = hlast + b * H_;
    const float* hb = hlast + (B_ + b) * H_;
    const float* wo = w_out + o * (2 * H_);
    float s = b_out[o];
#pragma unroll 8
    for (int j = 0; j < H_; j++) s += hf[j] * wo[j];
#pragma unroll 8
    for (int j = 0; j < H_; j++) s += hb[j] * wo[H_ + j];
    out[id] = s;
}

// ---------------------------------------------------------------------------
// Launch
// ---------------------------------------------------------------------------
extern "C" void kernel_launch(void* const* d_in, const int* in_sizes, int n_in,
                              void* d_out, int out_size)
{
    const float* data  = (const float*)d_in[0];
    const float* w_ih0 = (const float*)d_in[1];
    const float* w_hh0 = (const float*)d_in[2];
    const float* b_ih0 = (const float*)d_in[3];
    const float* b_hh0 = (const float*)d_in[4];
    const float* w_ih1 = (const float*)d_in[5];
    const float* w_hh1 = (const float*)d_in[6];
    const float* b_ih1 = (const float*)d_in[7];
    const float* b_hh1 = (const float*)d_in[8];
    const float* w_out = (const float*)d_in[9];
    const float* b_out = (const float*)d_in[10];
    float* out = (float*)d_out;

    float *px0, *px1, *y0, *hlast; unsigned *h, *fl;
    cudaGetSymbolAddress((void**)&px0,   g_px0);
    cudaGetSymbolAddress((void**)&px1,   g_px1);
    cudaGetSymbolAddress((void**)&y0,    g_y0);
    cudaGetSymbolAddress((void**)&h,     g_h);
    cudaGetSymbolAddress((void**)&hlast, g_hlast);
    cudaGetSymbolAddress((void**)&fl,    g_flags);

    cudaFuncSetAttribute(gemm_proj_tc, cudaFuncAttributeMaxDynamicSharedMemorySize,
                         TC_SMEM);
    cudaFuncSetAttribute(gru_scan_tc, cudaFuncAttributeMaxDynamicSharedMemorySize,
                         SCAN_SMEM_BYTES);

    zero_kernel<<<256, 256>>>();

    // Layer 0 input projection: M = B*T = 131072, K = 128
    dim3 gtc(1536 / 128, 131072 / 128);
    gemm_proj_tc<<<gtc, 256, TC_SMEM>>>(data, w_ih0, b_ih0, px0, IN_, 0);

    // Layer 0 bidirectional scan (writes y0)
    dim3 gs(8, 8, 2);
    const int hLayerStride = 2 * 2 * B_ * H_;
    const int fLayerStride = 2 * 8 * T_;
    gru_scan_tc<<<gs, 256, SCAN_SMEM_BYTES>>>(px0, w_hh0, b_hh0,
                                              h, fl, y0, nullptr);

    // Layer 1 input projection: M = T*B = 131072, K = 512
    gemm_proj_tc<<<gtc, 256, TC_SMEM>>>(y0, w_ih1, b_ih1, px1, 2 * H_, 1);

    // Layer 1 bidirectional scan (writes h_last only)
    gru_scan_tc<<<gs, 256, SCAN_SMEM_BYTES>>>(px1, w_hh1, b_hh1,
                                              h + hLayerStride, fl + fLayerStride,
                                              nullptr, hlast);

    // Output head
    head_kernel<<<2, 256>>>(hlast, w_out, b_out, out);
}